// round 1
// baseline (speedup 1.0000x reference)
#include <cuda_runtime.h>
#include <math.h>

#define BB 2
#define TT 2048
#define CC 1024
#define HH 16
#define DD 64

// Scratch (device globals: allocation-free per harness rules)
__device__ float g_q[(size_t)BB*HH*TT*DD];   // [B,H,T,D]
__device__ float g_k[(size_t)BB*HH*TT*DD];
__device__ float g_v[(size_t)BB*HH*TT*DD];
__device__ float g_y[(size_t)BB*TT*CC];      // [B,T,C] attention output

// ---------------------------------------------------------------------------
// SGEMM: C[M,N] = A[M,K] * W[N,K]^T   (both row-major, K contiguous)
// BM=BN=128, BK=16, 256 threads, 8x8 register tile per thread.
// EPI=0: plain store to C.  EPI=1: scatter into g_q/g_k/g_v ([B,H,T,D]).
// ---------------------------------------------------------------------------
template<int EPI>
__global__ __launch_bounds__(256, 2)
void sgemm_nt(const float* __restrict__ A, const float* __restrict__ W,
              float* __restrict__ C, int M, int N, int K)
{
    const int BM = 128, BN = 128, BK = 16;
    __shared__ float As[BK][BM + 4];   // +4 pad: conflict-free transposed stores
    __shared__ float Bs[BK][BN + 4];

    const int tid = threadIdx.x;
    const int tx = tid & 15, ty = tid >> 4;
    const int m0 = blockIdx.y * BM, n0 = blockIdx.x * BN;

    // load mapping: 2048 floats per tile = 512 float4; 2 float4 per thread
    const int lr = tid >> 2;        // row 0..63 (and +64)
    const int lc = (tid & 3) * 4;   // k-offset 0,4,8,12

    float acc[8][8];
#pragma unroll
    for (int i = 0; i < 8; i++)
#pragma unroll
        for (int j = 0; j < 8; j++) acc[i][j] = 0.f;

    for (int k0 = 0; k0 < K; k0 += BK) {
#pragma unroll
        for (int u = 0; u < 2; u++) {
            int row = lr + u * 64;
            float4 av = *(const float4*)(A + (size_t)(m0 + row) * K + k0 + lc);
            As[lc + 0][row] = av.x; As[lc + 1][row] = av.y;
            As[lc + 2][row] = av.z; As[lc + 3][row] = av.w;
            float4 bv = *(const float4*)(W + (size_t)(n0 + row) * K + k0 + lc);
            Bs[lc + 0][row] = bv.x; Bs[lc + 1][row] = bv.y;
            Bs[lc + 2][row] = bv.z; Bs[lc + 3][row] = bv.w;
        }
        __syncthreads();
#pragma unroll
        for (int k = 0; k < BK; k++) {
            float4 a0 = *(const float4*)&As[k][ty * 8];
            float4 a1 = *(const float4*)&As[k][ty * 8 + 4];
            float4 b0 = *(const float4*)&Bs[k][tx * 8];
            float4 b1 = *(const float4*)&Bs[k][tx * 8 + 4];
            float a[8] = {a0.x, a0.y, a0.z, a0.w, a1.x, a1.y, a1.z, a1.w};
            float b[8] = {b0.x, b0.y, b0.z, b0.w, b1.x, b1.y, b1.z, b1.w};
#pragma unroll
            for (int i = 0; i < 8; i++)
#pragma unroll
                for (int j = 0; j < 8; j++)
                    acc[i][j] += a[i] * b[j];
        }
        __syncthreads();
    }

    if (EPI == 0) {
#pragma unroll
        for (int i = 0; i < 8; i++) {
            int m = m0 + ty * 8 + i;
#pragma unroll
            for (int j = 0; j < 8; j++) {
                int n = n0 + tx * 8 + j;
                C[(size_t)m * N + n] = acc[i][j];
            }
        }
    } else {
        // qkv scatter: n in [0,3C); which = n/C; head = (n%C)/D; d = n%D
#pragma unroll
        for (int i = 0; i < 8; i++) {
            int m = m0 + ty * 8 + i;
            int b = m / TT, t = m % TT;
#pragma unroll
            for (int j = 0; j < 8; j++) {
                int n = n0 + tx * 8 + j;
                int which = n >> 10;        // /1024
                int rem = n & 1023;
                int h = rem >> 6, d = rem & 63;
                float* dst = (which == 0) ? g_q : ((which == 1) ? g_k : g_v);
                dst[(((size_t)b * HH + h) * TT + t) * DD + d] = acc[i][j];
            }
        }
    }
}

// ---------------------------------------------------------------------------
// Flash attention (fp32). CTA: 64 q-rows for one (b,h). 256 threads.
// S = (q.k^T + bias) * 8, causal mask, online softmax, y += P.V
// ---------------------------------------------------------------------------
#define ATTN_SMEM_FLOATS (4 * 64 * 65 + 3 * 64)

__global__ __launch_bounds__(256)
void attn_flash(const float* __restrict__ bias)
{
    extern __shared__ float sm[];
    float* qs    = sm;                 // [64][65]  (r, d)
    float* ks    = sm + 64 * 65;       // [64][65]  (s, d)
    float* vs    = sm + 2 * 64 * 65;   // [64][65]  (s, d)
    float* Ss    = sm + 3 * 64 * 65;   // [64][65]  (r, s)
    float* row_m = sm + 4 * 64 * 65;
    float* row_l = row_m + 64;
    float* row_sc = row_l + 64;

    const int tid = threadIdx.x;
    const int tx = tid & 15, ty = tid >> 4;
    const int t0 = blockIdx.x * 64;
    const int h = blockIdx.y, b = blockIdx.z;

    const float* qg = g_q + ((size_t)(b * HH + h) * TT + t0) * DD;
    const float* kg = g_k + (size_t)(b * HH + h) * TT * DD;
    const float* vg = g_v + (size_t)(b * HH + h) * TT * DD;
    const float* bptr = bias + ((size_t)h * TT + t0) * TT;

    // load q tile (64x64 contiguous floats)
#pragma unroll
    for (int u = 0; u < 4; u++) {
        int idx = tid + u * 256;          // float4 index 0..1023
        int r = idx >> 4, d4 = (idx & 15) * 4;
        float4 v4 = *(const float4*)(qg + r * 64 + d4);
        qs[r * 65 + d4 + 0] = v4.x; qs[r * 65 + d4 + 1] = v4.y;
        qs[r * 65 + d4 + 2] = v4.z; qs[r * 65 + d4 + 3] = v4.w;
    }
    if (tid < 64) { row_m[tid] = -INFINITY; row_l[tid] = 0.f; }

    float y[4][4];
#pragma unroll
    for (int i = 0; i < 4; i++)
#pragma unroll
        for (int j = 0; j < 4; j++) y[i][j] = 0.f;

    const int ntile = t0 / 64 + 1;   // causal: skip tiles fully above diagonal
    for (int it = 0; it < ntile; it++) {
        const int s0 = it * 64;
        // load K, V tiles
#pragma unroll
        for (int u = 0; u < 4; u++) {
            int idx = tid + u * 256;
            int r = idx >> 4, d4 = (idx & 15) * 4;
            float4 k4 = *(const float4*)(kg + (size_t)(s0 + r) * 64 + d4);
            ks[r * 65 + d4 + 0] = k4.x; ks[r * 65 + d4 + 1] = k4.y;
            ks[r * 65 + d4 + 2] = k4.z; ks[r * 65 + d4 + 3] = k4.w;
            float4 v4 = *(const float4*)(vg + (size_t)(s0 + r) * 64 + d4);
            vs[r * 65 + d4 + 0] = v4.x; vs[r * 65 + d4 + 1] = v4.y;
            vs[r * 65 + d4 + 2] = v4.z; vs[r * 65 + d4 + 3] = v4.w;
        }
        __syncthreads();

        // S = q.k^T (4x4 micro-tile per thread)
        float sacc[4][4];
#pragma unroll
        for (int i = 0; i < 4; i++)
#pragma unroll
            for (int j = 0; j < 4; j++) sacc[i][j] = 0.f;
#pragma unroll
        for (int d = 0; d < 64; d++) {
            float a[4], c[4];
#pragma unroll
            for (int i = 0; i < 4; i++) a[i] = qs[(ty * 4 + i) * 65 + d];
#pragma unroll
            for (int j = 0; j < 4; j++) c[j] = ks[(tx * 4 + j) * 65 + d];
#pragma unroll
            for (int i = 0; i < 4; i++)
#pragma unroll
                for (int j = 0; j < 4; j++)
                    sacc[i][j] += a[i] * c[j];
        }
        // bias + scale (x8, "divide by d^-0.5" quirk) + causal mask -> Ss
#pragma unroll
        for (int i = 0; i < 4; i++) {
            int r = ty * 4 + i;
            int t = t0 + r;
#pragma unroll
            for (int j = 0; j < 4; j++) {
                int c = tx * 4 + j;
                int s = s0 + c;
                float v = (sacc[i][j] + bptr[(size_t)r * TT + s]) * 8.0f;
                if (s > t) v = -1e30f;
                Ss[r * 65 + c] = v;
            }
        }
        __syncthreads();

        // online softmax state update (one thread per row)
        if (tid < 64) {
            int r = tid;
            float m_old = row_m[r];
            float m_new = m_old;
#pragma unroll 8
            for (int c = 0; c < 64; c++) m_new = fmaxf(m_new, Ss[r * 65 + c]);
            float sf = __expf(m_old - m_new);   // exp(-inf)=0 on first tile
            float sum = 0.f;
#pragma unroll 8
            for (int c = 0; c < 64; c++) {
                float p = __expf(Ss[r * 65 + c] - m_new);
                Ss[r * 65 + c] = p;
                sum += p;
            }
            row_l[r] = row_l[r] * sf + sum;
            row_m[r] = m_new;
            row_sc[r] = sf;
        }
        __syncthreads();

        // rescale accumulators, then y += P.V
#pragma unroll
        for (int i = 0; i < 4; i++) {
            float sf = row_sc[ty * 4 + i];
#pragma unroll
            for (int j = 0; j < 4; j++) y[i][j] *= sf;
        }
#pragma unroll
        for (int c = 0; c < 64; c++) {
            float p[4], vv[4];
#pragma unroll
            for (int i = 0; i < 4; i++) p[i] = Ss[(ty * 4 + i) * 65 + c];
#pragma unroll
            for (int j = 0; j < 4; j++) vv[j] = vs[c * 65 + tx * 4 + j];
#pragma unroll
            for (int i = 0; i < 4; i++)
#pragma unroll
                for (int j = 0; j < 4; j++)
                    y[i][j] += p[i] * vv[j];
        }
        __syncthreads();
    }

    // normalize and write y -> g_y [B,T,C] at column h*64+d
#pragma unroll
    for (int i = 0; i < 4; i++) {
        int r = ty * 4 + i;
        float inv = 1.0f / row_l[r];
#pragma unroll
        for (int j = 0; j < 4; j++) {
            g_y[((size_t)b * TT + t0 + r) * CC + h * 64 + tx * 4 + j] = y[i][j] * inv;
        }
    }
}

// ---------------------------------------------------------------------------
extern "C" void kernel_launch(void* const* d_in, const int* in_sizes, int n_in,
                              void* d_out, int out_size)
{
    const float* x    = (const float*)d_in[0];   // [B,T,C]
    const float* bias = (const float*)d_in[1];   // [1,H,T,T]
    const float* Wa   = (const float*)d_in[2];   // [3C,C]
    const float* Wp   = (const float*)d_in[3];   // [C,C]
    float* out = (float*)d_out;                  // [B,T,C]

    const int M = BB * TT;   // 4096

    // 1) QKV projection, scattered into g_q/g_k/g_v
    sgemm_nt<1><<<dim3(3 * CC / 128, M / 128), 256>>>(x, Wa, nullptr, M, 3 * CC, CC);

    // 2) flash attention
    const int smem_bytes = ATTN_SMEM_FLOATS * (int)sizeof(float);
    cudaFuncSetAttribute(attn_flash, cudaFuncAttributeMaxDynamicSharedMemorySize, smem_bytes);
    attn_flash<<<dim3(TT / 64, HH, BB), 256, smem_bytes>>>(bias);

    // 3) output projection
    void* y_addr = nullptr;
    cudaGetSymbolAddress(&y_addr, g_y);
    sgemm_nt<0><<<dim3(CC / 128, M / 128), 256>>>((const float*)y_addr, Wp, out, M, CC, CC);
}

// round 3
// speedup vs baseline: 2.7244x; 2.7244x over previous
#include <cuda_runtime.h>
#include <cuda_fp16.h>
#include <math.h>
#include <stdint.h>

#define BB 2
#define TT 2048
#define CC 1024
#define HH 16
#define DD 64

// ---------------- device scratch (allocation-free rule) ----------------
__device__ __half g_xh[4194304],  g_xl[4194304];    // x split        [4096][1024]
__device__ __half g_wah[3145728], g_wal[3145728];   // W_attn split   [3072][1024]
__device__ __half g_wph[1048576], g_wpl[1048576];   // W_proj split   [1024][1024]
__device__ __half g_qh[4194304],  g_ql[4194304];    // q split  [B,H,T,D]
__device__ __half g_kh[4194304],  g_kl[4194304];
__device__ __half g_vh[4194304],  g_vl[4194304];
__device__ __half g_yh[4194304],  g_yl[4194304];    // attn out split [4096][1024]

// ---------------- helpers ----------------
__device__ __forceinline__ uint32_t smem_u32(const void* p) {
    uint32_t a;
    asm("{ .reg .u64 t; cvta.to.shared.u64 t, %1; cvt.u32.u64 %0, t; }" : "=r"(a) : "l"(p));
    return a;
}

__device__ __forceinline__ void mma_f16(float* c, const uint32_t* a, uint32_t b0, uint32_t b1) {
    asm volatile(
        "mma.sync.aligned.m16n8k16.row.col.f32.f16.f16.f32 "
        "{%0,%1,%2,%3}, {%4,%5,%6,%7}, {%8,%9}, {%0,%1,%2,%3};\n"
        : "+f"(c[0]), "+f"(c[1]), "+f"(c[2]), "+f"(c[3])
        : "r"(a[0]), "r"(a[1]), "r"(a[2]), "r"(a[3]), "r"(b0), "r"(b1));
}
__device__ __forceinline__ void ldsm4(uint32_t* r, uint32_t addr) {
    asm volatile("ldmatrix.sync.aligned.m8n8.x4.shared.b16 {%0,%1,%2,%3}, [%4];"
                 : "=r"(r[0]), "=r"(r[1]), "=r"(r[2]), "=r"(r[3]) : "r"(addr));
}
__device__ __forceinline__ void ldsm4t(uint32_t* r, uint32_t addr) {
    asm volatile("ldmatrix.sync.aligned.m8n8.x4.trans.shared.b16 {%0,%1,%2,%3}, [%4];"
                 : "=r"(r[0]), "=r"(r[1]), "=r"(r[2]), "=r"(r[3]) : "r"(addr));
}
#define CP16(sa, g) asm volatile("cp.async.cg.shared.global [%0], [%1], 16;" :: "r"(sa), "l"(g) : "memory")
#define CP_COMMIT() asm volatile("cp.async.commit_group;" ::: "memory")
#define CP_WAIT1()  asm volatile("cp.async.wait_group 1;" ::: "memory")
#define CP_WAIT0()  asm volatile("cp.async.wait_group 0;" ::: "memory")

__device__ __forceinline__ void split_pack(float a, float b, uint32_t& hi, uint32_t& lo) {
    __half ha = __float2half_rn(a), hb = __float2half_rn(b);
    __half la = __float2half_rn(a - __half2float(ha));
    __half lb = __float2half_rn(b - __half2float(hb));
    __half2 H = __halves2half2(ha, hb), L = __halves2half2(la, lb);
    hi = *(uint32_t*)&H;  lo = *(uint32_t*)&L;
}

// ---------------- fp32 -> fp16 hi/lo split ----------------
__global__ void split2h(const float* __restrict__ s, __half* __restrict__ hi,
                        __half* __restrict__ lo, int n) {
    int i = blockIdx.x * blockDim.x + threadIdx.x;
    if (i < n) {
        float v = s[i];
        __half h = __float2half_rn(v);
        hi[i] = h;
        lo[i] = __float2half_rn(v - __half2float(h));
    }
}

// ---------------------------------------------------------------------------
// HMMA fp16x2 GEMM: C[M,N] = A[M,K]*B[N,K]^T (3-pass split, fp32 accum)
// CTA 128x128, 256 threads (8 warps, 4m x 2n), K-chunk 64, double-buffered.
// EPI=0: fp32 store to C.  EPI=1: split-store into g_{q,k,v}{h,l} [B,H,T,D].
// ---------------------------------------------------------------------------
#define GEMM_SMEM (2 * 65536)

template<int EPI>
__global__ __launch_bounds__(256)
void gemm_h2(const __half* __restrict__ Ah, const __half* __restrict__ Al,
             const __half* __restrict__ Bh_, const __half* __restrict__ Bl_,
             float* __restrict__ C, int M, int N, int K)
{
    extern __shared__ char smem[];
    const uint32_t sb = smem_u32(smem);
    const int tid = threadIdx.x, lane = tid & 31, wid = tid >> 5;
    const int wm = wid >> 1, wn = wid & 1;
    const int m0 = blockIdx.y * 128, n0 = blockIdx.x * 128;

    const __half* srcs[4] = {Ah, Al, Bh_, Bl_};

    auto issue = [&](int buf, int k0) {
#pragma unroll
        for (int p = 0; p < 4; p++) {
            const int rb = (p < 2) ? m0 : n0;
            const __half* S = srcs[p];
#pragma unroll
            for (int u = 0; u < 4; u++) {
                int unit = tid + u * 256;            // 0..1023
                int r = unit >> 3, sg = unit & 7;
                uint32_t sa = sb + (uint32_t)(buf * 65536 + p * 16384) + r * 128 + (((sg ^ (r & 7))) << 4);
                const void* g = (const void*)(S + (size_t)(rb + r) * K + k0 + sg * 8);
                CP16(sa, g);
            }
        }
        CP_COMMIT();
    };

    float acc[2][8][4];
#pragma unroll
    for (int mt = 0; mt < 2; mt++)
#pragma unroll
        for (int nt = 0; nt < 8; nt++)
#pragma unroll
            for (int j = 0; j < 4; j++) acc[mt][nt][j] = 0.f;

    const int NC = K >> 6;
    issue(0, 0);
    for (int kc = 0; kc < NC; kc++) {
        const int buf = kc & 1;
        if (kc + 1 < NC) { issue(buf ^ 1, (kc + 1) * 64); CP_WAIT1(); }
        else CP_WAIT0();
        __syncthreads();

        const uint32_t Ab = sb + (uint32_t)(buf * 65536);
        const uint32_t Bb = Ab + 32768;
#pragma unroll
        for (int ks = 0; ks < 4; ks++) {
            uint32_t Af[2][2][4];   // [part][mt]
#pragma unroll
            for (int p = 0; p < 2; p++)
#pragma unroll
                for (int mt = 0; mt < 2; mt++) {
                    int row = wm * 32 + mt * 16 + (lane & 15);
                    int un = (ks * 2 + (lane >> 4)) ^ (row & 7);
                    ldsm4(Af[p][mt], Ab + (uint32_t)(p * 16384) + row * 128 + un * 16);
                }
            uint32_t Bf[2][4][4];   // [part][group of 2 n-tiles]
#pragma unroll
            for (int p = 0; p < 2; p++)
#pragma unroll
                for (int g = 0; g < 4; g++) {
                    int row = wn * 64 + g * 16 + (lane & 15);
                    int un = (ks * 2 + (lane >> 4)) ^ (row & 7);
                    ldsm4(Bf[p][g], Bb + (uint32_t)(p * 16384) + row * 128 + un * 16);
                }
            // 3 passes: (Ah,Bh), (Ah,Bl), (Al,Bh) — interleaved accs per pass
#pragma unroll
            for (int pass = 0; pass < 3; pass++) {
                const int ap = (pass == 2) ? 1 : 0;
                const int bp = (pass == 1) ? 1 : 0;
#pragma unroll
                for (int mt = 0; mt < 2; mt++)
#pragma unroll
                    for (int g = 0; g < 4; g++) {
                        mma_f16(acc[mt][2 * g],     Af[ap][mt], Bf[bp][g][0], Bf[bp][g][2]);
                        mma_f16(acc[mt][2 * g + 1], Af[ap][mt], Bf[bp][g][1], Bf[bp][g][3]);
                    }
            }
        }
        __syncthreads();
    }

    // epilogue
#pragma unroll
    for (int mt = 0; mt < 2; mt++) {
        int r0 = m0 + wm * 32 + mt * 16 + (lane >> 2);
        int r1 = r0 + 8;
#pragma unroll
        for (int nt = 0; nt < 8; nt++) {
            int n = n0 + wn * 64 + nt * 8 + (lane & 3) * 2;
            if (EPI == 0) {
                *(float2*)(C + (size_t)r0 * N + n) = make_float2(acc[mt][nt][0], acc[mt][nt][1]);
                *(float2*)(C + (size_t)r1 * N + n) = make_float2(acc[mt][nt][2], acc[mt][nt][3]);
            } else {
                int which = n >> 10, rem = n & 1023;
                int h = rem >> 6, d = rem & 63;
                __half* dh = (which == 0) ? g_qh : ((which == 1) ? g_kh : g_vh);
                __half* dl = (which == 0) ? g_ql : ((which == 1) ? g_kl : g_vl);
#pragma unroll
                for (int half_ = 0; half_ < 2; half_++) {
                    int m = half_ ? r1 : r0;
                    float v0 = acc[mt][nt][half_ * 2], v1 = acc[mt][nt][half_ * 2 + 1];
                    int b = m >> 11, t = m & 2047;
                    size_t idx = (((size_t)b * HH + h) * TT + t) * DD + d;
                    uint32_t hpk, lpk;
                    split_pack(v0, v1, hpk, lpk);
                    *(uint32_t*)(dh + idx) = hpk;
                    *(uint32_t*)(dl + idx) = lpk;
                }
            }
        }
    }
}

// ---------------------------------------------------------------------------
// Flash attention on HMMA (fp16x2 3-pass). CTA: 64 q-rows, 128 threads.
// smem: Q hi/lo (2x8KB) + KV double buffer (2 x 4 parts x 8KB) = 80KB
// ---------------------------------------------------------------------------
#define ATTN_SMEM (16384 + 2 * 32768)

__global__ __launch_bounds__(128)
void attn_mma(const float* __restrict__ bias)
{
    extern __shared__ char smem[];
    const uint32_t sb = smem_u32(smem);
    const int tid = threadIdx.x, lane = tid & 31, wid = tid >> 5;
    const int t0 = blockIdx.x * 64, h = blockIdx.y, b = blockIdx.z;

    const size_t qoff  = ((size_t)(b * HH + h) * TT + t0) * DD;
    const size_t kvoff = (size_t)(b * HH + h) * TT * DD;

    // Q load (both parts) into smem — joins KV0's cp.async group
    {
        const __half* S[2] = {g_qh + qoff, g_ql + qoff};
#pragma unroll
        for (int p = 0; p < 2; p++)
#pragma unroll
            for (int u = 0; u < 4; u++) {
                int unit = tid + u * 128;          // 0..511
                int r = unit >> 3, sg = unit & 7;
                uint32_t sa = sb + (uint32_t)(p * 8192) + r * 128 + ((sg ^ (r & 7)) << 4);
                CP16(sa, (const void*)(S[p] + (size_t)r * 64 + sg * 8));
            }
    }
    const __half* kvsrc[4] = {g_kh + kvoff, g_kl + kvoff, g_vh + kvoff, g_vl + kvoff};
    auto kv_issue = [&](int buf, int s0) {
#pragma unroll
        for (int p = 0; p < 4; p++) {
            const __half* S = kvsrc[p] + (size_t)s0 * 64;
#pragma unroll
            for (int u = 0; u < 4; u++) {
                int unit = tid + u * 128;
                int r = unit >> 3, sg = unit & 7;
                uint32_t sa = sb + 16384u + (uint32_t)(buf * 32768 + p * 8192) + r * 128 + ((sg ^ (r & 7)) << 4);
                CP16(sa, (const void*)(S + (size_t)r * 64 + sg * 8));
            }
        }
        CP_COMMIT();
    };
    kv_issue(0, 0);

    float m0r = -1e30f, m1r = -1e30f, l0r = 0.f, l1r = 0.f;
    float y[8][4];
#pragma unroll
    for (int nt = 0; nt < 8; nt++)
#pragma unroll
        for (int j = 0; j < 4; j++) y[nt][j] = 0.f;

    uint32_t Qf[2][4][4];    // [part][ks]
    const int r0g = t0 + wid * 16 + (lane >> 2);
    const int r1g = r0g + 8;
    const int ntiles = t0 / 64 + 1;

    for (int it = 0; it < ntiles; it++) {
        if (it + 1 < ntiles) { kv_issue((it + 1) & 1, (it + 1) * 64); CP_WAIT1(); }
        else CP_WAIT0();
        __syncthreads();

        if (it == 0) {
#pragma unroll
            for (int p = 0; p < 2; p++)
#pragma unroll
                for (int ks = 0; ks < 4; ks++) {
                    int row = wid * 16 + (lane & 15);
                    int un = (ks * 2 + (lane >> 4)) ^ (row & 7);
                    ldsm4(Qf[p][ks], sb + (uint32_t)(p * 8192) + row * 128 + un * 16);
                }
        }
        const uint32_t Kb = sb + 16384u + (uint32_t)((it & 1) * 32768);
        const uint32_t Vb = Kb + 16384u;

        // ---- S = Q.K^T ----
        float S[8][4];
#pragma unroll
        for (int nt = 0; nt < 8; nt++)
#pragma unroll
            for (int j = 0; j < 4; j++) S[nt][j] = 0.f;
#pragma unroll
        for (int ks = 0; ks < 4; ks++) {
            uint32_t Bf[2][4][4];
#pragma unroll
            for (int p = 0; p < 2; p++)
#pragma unroll
                for (int g = 0; g < 4; g++) {
                    int row = g * 16 + (lane & 15);
                    int un = (ks * 2 + (lane >> 4)) ^ (row & 7);
                    ldsm4(Bf[p][g], Kb + (uint32_t)(p * 8192) + row * 128 + un * 16);
                }
#pragma unroll
            for (int pass = 0; pass < 3; pass++) {
                const int ap = (pass == 2) ? 1 : 0;
                const int bp = (pass == 1) ? 1 : 0;
#pragma unroll
                for (int g = 0; g < 4; g++) {
                    mma_f16(S[2 * g],     Qf[ap][ks], Bf[bp][g][0], Bf[bp][g][2]);
                    mma_f16(S[2 * g + 1], Qf[ap][ks], Bf[bp][g][1], Bf[bp][g][3]);
                }
            }
        }

        // ---- bias + scale + causal mask ----
        const bool diag = (it == ntiles - 1);
#pragma unroll
        for (int nt = 0; nt < 8; nt++) {
            int cg = it * 64 + nt * 8 + (lane & 3) * 2;
            float2 b0 = *(const float2*)(bias + ((size_t)h * TT + r0g) * TT + cg);
            float2 b1 = *(const float2*)(bias + ((size_t)h * TT + r1g) * TT + cg);
            S[nt][0] = (S[nt][0] + b0.x) * 8.f;
            S[nt][1] = (S[nt][1] + b0.y) * 8.f;
            S[nt][2] = (S[nt][2] + b1.x) * 8.f;
            S[nt][3] = (S[nt][3] + b1.y) * 8.f;
            if (diag) {
                if (cg     > r0g) S[nt][0] = -1e30f;
                if (cg + 1 > r0g) S[nt][1] = -1e30f;
                if (cg     > r1g) S[nt][2] = -1e30f;
                if (cg + 1 > r1g) S[nt][3] = -1e30f;
            }
        }

        // ---- online softmax (rows r0g / r1g; quad shares a row) ----
        float mx0 = -1e30f, mx1 = -1e30f;
#pragma unroll
        for (int nt = 0; nt < 8; nt++) {
            mx0 = fmaxf(mx0, fmaxf(S[nt][0], S[nt][1]));
            mx1 = fmaxf(mx1, fmaxf(S[nt][2], S[nt][3]));
        }
        mx0 = fmaxf(mx0, __shfl_xor_sync(0xFFFFFFFF, mx0, 1));
        mx0 = fmaxf(mx0, __shfl_xor_sync(0xFFFFFFFF, mx0, 2));
        mx1 = fmaxf(mx1, __shfl_xor_sync(0xFFFFFFFF, mx1, 1));
        mx1 = fmaxf(mx1, __shfl_xor_sync(0xFFFFFFFF, mx1, 2));
        float mn0 = fmaxf(m0r, mx0), mn1 = fmaxf(m1r, mx1);
        float sc0 = __expf(m0r - mn0), sc1 = __expf(m1r - mn1);
        m0r = mn0; m1r = mn1;

        float sum0 = 0.f, sum1 = 0.f;
        uint32_t Ph[4][4], Pl[4][4];
#pragma unroll
        for (int ks = 0; ks < 4; ks++) {
#pragma unroll
            for (int half_ = 0; half_ < 2; half_++) {
                int nt = 2 * ks + half_;
                float p0 = __expf(S[nt][0] - mn0);
                float p1 = __expf(S[nt][1] - mn0);
                float p2 = __expf(S[nt][2] - mn1);
                float p3 = __expf(S[nt][3] - mn1);
                sum0 += p0 + p1; sum1 += p2 + p3;
                split_pack(p0, p1, Ph[ks][half_ * 2],     Pl[ks][half_ * 2]);
                split_pack(p2, p3, Ph[ks][half_ * 2 + 1], Pl[ks][half_ * 2 + 1]);
            }
        }
        sum0 += __shfl_xor_sync(0xFFFFFFFF, sum0, 1);
        sum0 += __shfl_xor_sync(0xFFFFFFFF, sum0, 2);
        sum1 += __shfl_xor_sync(0xFFFFFFFF, sum1, 1);
        sum1 += __shfl_xor_sync(0xFFFFFFFF, sum1, 2);
        l0r = l0r * sc0 + sum0;
        l1r = l1r * sc1 + sum1;
#pragma unroll
        for (int nt = 0; nt < 8; nt++) {
            y[nt][0] *= sc0; y[nt][1] *= sc0;
            y[nt][2] *= sc1; y[nt][3] *= sc1;
        }

        // ---- y += P.V  (V via ldmatrix.trans) ----
#pragma unroll
        for (int ks = 0; ks < 4; ks++) {
            uint32_t Vf[2][4][4];
#pragma unroll
            for (int p = 0; p < 2; p++)
#pragma unroll
                for (int dc = 0; dc < 4; dc++) {
                    int row = ks * 16 + (lane & 15);
                    int un = (2 * dc + (lane >> 4)) ^ (row & 7);
                    ldsm4t(Vf[p][dc], Vb + (uint32_t)(p * 8192) + row * 128 + un * 16);
                }
#pragma unroll
            for (int pass = 0; pass < 3; pass++) {
                const uint32_t* A = (pass == 2) ? Pl[ks] : Ph[ks];
                const int vp = (pass == 1) ? 1 : 0;
#pragma unroll
                for (int dc = 0; dc < 4; dc++) {
                    mma_f16(y[2 * dc],     A, Vf[vp][dc][0], Vf[vp][dc][1]);
                    mma_f16(y[2 * dc + 1], A, Vf[vp][dc][2], Vf[vp][dc][3]);
                }
            }
        }
        __syncthreads();
    }

    // ---- normalize, split-store to g_yh/g_yl [B*T][C] ----
    float inv0 = 1.f / l0r, inv1 = 1.f / l1r;
#pragma unroll
    for (int nt = 0; nt < 8; nt++) {
        int col = h * 64 + nt * 8 + (lane & 3) * 2;
        size_t row0 = (size_t)b * TT + r0g;
        size_t row1 = (size_t)b * TT + r1g;
        uint32_t hpk, lpk;
        split_pack(y[nt][0] * inv0, y[nt][1] * inv0, hpk, lpk);
        *(uint32_t*)(g_yh + row0 * CC + col) = hpk;
        *(uint32_t*)(g_yl + row0 * CC + col) = lpk;
        split_pack(y[nt][2] * inv1, y[nt][3] * inv1, hpk, lpk);
        *(uint32_t*)(g_yh + row1 * CC + col) = hpk;
        *(uint32_t*)(g_yl + row1 * CC + col) = lpk;
    }
}

// ---------------------------------------------------------------------------
extern "C" void kernel_launch(void* const* d_in, const int* in_sizes, int n_in,
                              void* d_out, int out_size)
{
    const float* x    = (const float*)d_in[0];   // [B,T,C]
    const float* bias = (const float*)d_in[1];   // [1,H,T,T]
    const float* Wa   = (const float*)d_in[2];   // [3C,C]
    const float* Wp   = (const float*)d_in[3];   // [C,C]
    float* out = (float*)d_out;

    const int M = BB * TT;   // 4096

    void *xh, *xl, *wah, *wal, *wph, *wpl, *yh, *yl;
    cudaGetSymbolAddress(&xh, g_xh);   cudaGetSymbolAddress(&xl, g_xl);
    cudaGetSymbolAddress(&wah, g_wah); cudaGetSymbolAddress(&wal, g_wal);
    cudaGetSymbolAddress(&wph, g_wph); cudaGetSymbolAddress(&wpl, g_wpl);
    cudaGetSymbolAddress(&yh, g_yh);   cudaGetSymbolAddress(&yl, g_yl);

    cudaFuncSetAttribute(gemm_h2<1>, cudaFuncAttributeMaxDynamicSharedMemorySize, GEMM_SMEM);
    cudaFuncSetAttribute(gemm_h2<0>, cudaFuncAttributeMaxDynamicSharedMemorySize, GEMM_SMEM);
    cudaFuncSetAttribute(attn_mma,   cudaFuncAttributeMaxDynamicSharedMemorySize, ATTN_SMEM);

    // 0) fp32 -> fp16 hi/lo splits of inputs
    split2h<<<(M * CC + 255) / 256, 256>>>(x,  (__half*)xh,  (__half*)xl,  M * CC);
    split2h<<<(3 * CC * CC + 255) / 256, 256>>>(Wa, (__half*)wah, (__half*)wal, 3 * CC * CC);
    split2h<<<(CC * CC + 255) / 256, 256>>>(Wp, (__half*)wph, (__half*)wpl, CC * CC);

    // 1) QKV projection -> split q/k/v in [B,H,T,D]
    gemm_h2<1><<<dim3(3 * CC / 128, M / 128), 256, GEMM_SMEM>>>(
        (const __half*)xh, (const __half*)xl,
        (const __half*)wah, (const __half*)wal, nullptr, M, 3 * CC, CC);

    // 2) flash attention (HMMA) -> split y
    attn_mma<<<dim3(TT / 64, HH, BB), 128, ATTN_SMEM>>>(bias);

    // 3) output projection -> fp32 out
    gemm_h2<0><<<dim3(CC / 128, M / 128), 256, GEMM_SMEM>>>(
        (const __half*)yh, (const __half*)yl,
        (const __half*)wph, (const __half*)wpl, out, M, CC, CC);
}

// round 4
// speedup vs baseline: 2.9021x; 1.0652x over previous
#include <cuda_runtime.h>
#include <cuda_fp16.h>
#include <math.h>
#include <stdint.h>

#define BB 2
#define TT 2048
#define CC 1024
#define HH 16
#define DD 64

// ---------------- device scratch (allocation-free rule) ----------------
__device__ __half g_xh[4194304],  g_xl[4194304];    // x split        [4096][1024]
__device__ __half g_wah[3145728], g_wal[3145728];   // W_attn split   [3072][1024]
__device__ __half g_wph[1048576], g_wpl[1048576];   // W_proj split   [1024][1024]
__device__ __half g_qh[4194304],  g_ql[4194304];    // q split  [B,H,T,D]
__device__ __half g_kh[4194304],  g_kl[4194304];
__device__ __half g_vh[4194304],  g_vl[4194304];
__device__ __half g_yh[4194304],  g_yl[4194304];    // attn out split [4096][1024]

// ---------------- helpers ----------------
__device__ __forceinline__ uint32_t smem_u32(const void* p) {
    uint32_t a;
    asm("{ .reg .u64 t; cvta.to.shared.u64 t, %1; cvt.u32.u64 %0, t; }" : "=r"(a) : "l"(p));
    return a;
}

__device__ __forceinline__ void mma_f16(float* c, const uint32_t* a, uint32_t b0, uint32_t b1) {
    asm volatile(
        "mma.sync.aligned.m16n8k16.row.col.f32.f16.f16.f32 "
        "{%0,%1,%2,%3}, {%4,%5,%6,%7}, {%8,%9}, {%0,%1,%2,%3};\n"
        : "+f"(c[0]), "+f"(c[1]), "+f"(c[2]), "+f"(c[3])
        : "r"(a[0]), "r"(a[1]), "r"(a[2]), "r"(a[3]), "r"(b0), "r"(b1));
}
__device__ __forceinline__ void ldsm4(uint32_t* r, uint32_t addr) {
    asm volatile("ldmatrix.sync.aligned.m8n8.x4.shared.b16 {%0,%1,%2,%3}, [%4];"
                 : "=r"(r[0]), "=r"(r[1]), "=r"(r[2]), "=r"(r[3]) : "r"(addr));
}
__device__ __forceinline__ void ldsm4t(uint32_t* r, uint32_t addr) {
    asm volatile("ldmatrix.sync.aligned.m8n8.x4.trans.shared.b16 {%0,%1,%2,%3}, [%4];"
                 : "=r"(r[0]), "=r"(r[1]), "=r"(r[2]), "=r"(r[3]) : "r"(addr));
}
#define CP16(sa, g) asm volatile("cp.async.cg.shared.global [%0], [%1], 16;" :: "r"(sa), "l"(g) : "memory")
#define CP_COMMIT() asm volatile("cp.async.commit_group;" ::: "memory")
#define CP_WAIT1()  asm volatile("cp.async.wait_group 1;" ::: "memory")
#define CP_WAIT0()  asm volatile("cp.async.wait_group 0;" ::: "memory")

__device__ __forceinline__ void split_pack(float a, float b, uint32_t& hi, uint32_t& lo) {
    __half ha = __float2half_rn(a), hb = __float2half_rn(b);
    __half la = __float2half_rn(a - __half2float(ha));
    __half lb = __float2half_rn(b - __half2float(hb));
    __half2 H = __halves2half2(ha, hb), L = __halves2half2(la, lb);
    hi = *(uint32_t*)&H;  lo = *(uint32_t*)&L;
}
__device__ __forceinline__ uint32_t pack2h(float a, float b) {
    __half2 H = __halves2half2(__float2half_rn(a), __float2half_rn(b));
    return *(uint32_t*)&H;
}

// ---------------- fp32 -> fp16 hi/lo split ----------------
__global__ void split2h(const float* __restrict__ s, __half* __restrict__ hi,
                        __half* __restrict__ lo, int n) {
    int i = blockIdx.x * blockDim.x + threadIdx.x;
    if (i < n) {
        float v = s[i];
        __half h = __float2half_rn(v);
        hi[i] = h;
        lo[i] = __float2half_rn(v - __half2float(h));
    }
}

// ---------------------------------------------------------------------------
// HMMA fp16x2 GEMM: C[M,N] = A[M,K]*B[N,K]^T (3-pass split, fp32 accum)
// CTA 128x128, 256 threads (8 warps, 4m x 2n), K-chunk 64, double-buffered
// smem AND double-buffered register fragments (LDSM prefetch of ks+1).
// EPI=0: fp32 store to C.  EPI=1: split-store into g_{q,k,v}{h,l} [B,H,T,D].
// ---------------------------------------------------------------------------
#define GEMM_SMEM (2 * 65536)

template<int EPI>
__global__ __launch_bounds__(256, 1)
void gemm_h2(const __half* __restrict__ Ah, const __half* __restrict__ Al,
             const __half* __restrict__ Bh_, const __half* __restrict__ Bl_,
             float* __restrict__ C, int M, int N, int K)
{
    extern __shared__ char smem[];
    const uint32_t sb = smem_u32(smem);
    const int tid = threadIdx.x, lane = tid & 31, wid = tid >> 5;
    const int wm = wid >> 1, wn = wid & 1;
    const int m0 = blockIdx.y * 128, n0 = blockIdx.x * 128;

    const __half* srcs[4] = {Ah, Al, Bh_, Bl_};

    auto issue = [&](int buf, int k0) {
#pragma unroll
        for (int p = 0; p < 4; p++) {
            const int rb = (p < 2) ? m0 : n0;
            const __half* S = srcs[p];
#pragma unroll
            for (int u = 0; u < 4; u++) {
                int unit = tid + u * 256;            // 0..1023
                int r = unit >> 3, sg = unit & 7;
                uint32_t sa = sb + (uint32_t)(buf * 65536 + p * 16384) + r * 128 + (((sg ^ (r & 7))) << 4);
                const void* g = (const void*)(S + (size_t)(rb + r) * K + k0 + sg * 8);
                CP16(sa, g);
            }
        }
        CP_COMMIT();
    };

    float acc[2][8][4];
#pragma unroll
    for (int mt = 0; mt < 2; mt++)
#pragma unroll
        for (int nt = 0; nt < 8; nt++)
#pragma unroll
            for (int j = 0; j < 4; j++) acc[mt][nt][j] = 0.f;

    uint32_t Af[2][2][2][4];   // [frag buf][part][mt]
    uint32_t Bf[2][2][4][4];   // [frag buf][part][g]

    const int NC = K >> 6;
    issue(0, 0);
    for (int kc = 0; kc < NC; kc++) {
        const int buf = kc & 1;
        if (kc + 1 < NC) { issue(buf ^ 1, (kc + 1) * 64); CP_WAIT1(); }
        else CP_WAIT0();
        __syncthreads();

        const uint32_t Ab = sb + (uint32_t)(buf * 65536);
        const uint32_t Bb = Ab + 32768;

        auto load_frags = [&](int ks, int fb) {
#pragma unroll
            for (int p = 0; p < 2; p++) {
#pragma unroll
                for (int mt = 0; mt < 2; mt++) {
                    int row = wm * 32 + mt * 16 + (lane & 15);
                    int un = (ks * 2 + (lane >> 4)) ^ (row & 7);
                    ldsm4(Af[fb][p][mt], Ab + (uint32_t)(p * 16384) + row * 128 + un * 16);
                }
#pragma unroll
                for (int g = 0; g < 4; g++) {
                    int row = wn * 64 + g * 16 + (lane & 15);
                    int un = (ks * 2 + (lane >> 4)) ^ (row & 7);
                    ldsm4(Bf[fb][p][g], Bb + (uint32_t)(p * 16384) + row * 128 + un * 16);
                }
            }
        };

        load_frags(0, 0);
#pragma unroll
        for (int ks = 0; ks < 4; ks++) {
            const int cur = ks & 1;
            if (ks < 3) load_frags(ks + 1, cur ^ 1);   // prefetch: hides LDSM latency
#pragma unroll
            for (int pass = 0; pass < 3; pass++) {
                const int ap = (pass == 2) ? 1 : 0;
                const int bp = (pass == 1) ? 1 : 0;
#pragma unroll
                for (int mt = 0; mt < 2; mt++)
#pragma unroll
                    for (int g = 0; g < 4; g++) {
                        mma_f16(acc[mt][2 * g],     Af[cur][ap][mt], Bf[cur][bp][g][0], Bf[cur][bp][g][2]);
                        mma_f16(acc[mt][2 * g + 1], Af[cur][ap][mt], Bf[cur][bp][g][1], Bf[cur][bp][g][3]);
                    }
            }
        }
        __syncthreads();
    }

    // epilogue
#pragma unroll
    for (int mt = 0; mt < 2; mt++) {
        int r0 = m0 + wm * 32 + mt * 16 + (lane >> 2);
        int r1 = r0 + 8;
#pragma unroll
        for (int nt = 0; nt < 8; nt++) {
            int n = n0 + wn * 64 + nt * 8 + (lane & 3) * 2;
            if (EPI == 0) {
                *(float2*)(C + (size_t)r0 * N + n) = make_float2(acc[mt][nt][0], acc[mt][nt][1]);
                *(float2*)(C + (size_t)r1 * N + n) = make_float2(acc[mt][nt][2], acc[mt][nt][3]);
            } else {
                int which = n >> 10, rem = n & 1023;
                int h = rem >> 6, d = rem & 63;
                __half* dh = (which == 0) ? g_qh : ((which == 1) ? g_kh : g_vh);
                __half* dl = (which == 0) ? g_ql : ((which == 1) ? g_kl : g_vl);
#pragma unroll
                for (int half_ = 0; half_ < 2; half_++) {
                    int m = half_ ? r1 : r0;
                    float v0 = acc[mt][nt][half_ * 2], v1 = acc[mt][nt][half_ * 2 + 1];
                    int b = m >> 11, t = m & 2047;
                    size_t idx = (((size_t)b * HH + h) * TT + t) * DD + d;
                    uint32_t hpk, lpk;
                    split_pack(v0, v1, hpk, lpk);
                    *(uint32_t*)(dh + idx) = hpk;
                    *(uint32_t*)(dl + idx) = lpk;
                }
            }
        }
    }
}

// ---------------------------------------------------------------------------
// Flash attention on HMMA. CTA: 64 q-rows, 128 threads.
// QK^T: 3-pass fp16x2.  PV: 2-pass (Ph*Vh + Ph*Vl).
// K-fragment double buffering + bias prefetch. Reversed CTA order.
// smem: Q hi/lo (2x8KB) + KV double buffer (2 x 4 parts x 8KB) = 80KB
// ---------------------------------------------------------------------------
#define ATTN_SMEM (16384 + 2 * 32768)

__global__ __launch_bounds__(128)
void attn_mma(const float* __restrict__ bias)
{
    extern __shared__ char smem[];
    const uint32_t sb = smem_u32(smem);
    const int tid = threadIdx.x, lane = tid & 31, wid = tid >> 5;
    const int t0 = (int)(gridDim.x - 1 - blockIdx.x) * 64;   // heavy tiles first
    const int h = blockIdx.y, b = blockIdx.z;

    const size_t qoff  = ((size_t)(b * HH + h) * TT + t0) * DD;
    const size_t kvoff = (size_t)(b * HH + h) * TT * DD;

    // Q load (both parts) into smem — joins KV0's cp.async group
    {
        const __half* S[2] = {g_qh + qoff, g_ql + qoff};
#pragma unroll
        for (int p = 0; p < 2; p++)
#pragma unroll
            for (int u = 0; u < 4; u++) {
                int unit = tid + u * 128;          // 0..511
                int r = unit >> 3, sg = unit & 7;
                uint32_t sa = sb + (uint32_t)(p * 8192) + r * 128 + ((sg ^ (r & 7)) << 4);
                CP16(sa, (const void*)(S[p] + (size_t)r * 64 + sg * 8));
            }
    }
    const __half* kvsrc[4] = {g_kh + kvoff, g_kl + kvoff, g_vh + kvoff, g_vl + kvoff};
    auto kv_issue = [&](int buf, int s0) {
#pragma unroll
        for (int p = 0; p < 4; p++) {
            const __half* S = kvsrc[p] + (size_t)s0 * 64;
#pragma unroll
            for (int u = 0; u < 4; u++) {
                int unit = tid + u * 128;
                int r = unit >> 3, sg = unit & 7;
                uint32_t sa = sb + 16384u + (uint32_t)(buf * 32768 + p * 8192) + r * 128 + ((sg ^ (r & 7)) << 4);
                CP16(sa, (const void*)(S + (size_t)r * 64 + sg * 8));
            }
        }
        CP_COMMIT();
    };
    kv_issue(0, 0);

    float m0r = -1e30f, m1r = -1e30f, l0r = 0.f, l1r = 0.f;
    float y[8][4];
#pragma unroll
    for (int nt = 0; nt < 8; nt++)
#pragma unroll
        for (int j = 0; j < 4; j++) y[nt][j] = 0.f;

    uint32_t Qf[2][4][4];    // [part][ks]
    const int r0g = t0 + wid * 16 + (lane >> 2);
    const int r1g = r0g + 8;
    const int ntiles = t0 / 64 + 1;
    const float* brow0 = bias + ((size_t)h * TT + r0g) * TT + (lane & 3) * 2;
    const float* brow1 = bias + ((size_t)h * TT + r1g) * TT + (lane & 3) * 2;

    for (int it = 0; it < ntiles; it++) {
        if (it + 1 < ntiles) { kv_issue((it + 1) & 1, (it + 1) * 64); CP_WAIT1(); }
        else CP_WAIT0();
        __syncthreads();

        // bias prefetch (gmem latency hidden under S MMAs)
        float2 bv0[8], bv1[8];
#pragma unroll
        for (int nt = 0; nt < 8; nt++) {
            bv0[nt] = *(const float2*)(brow0 + it * 64 + nt * 8);
            bv1[nt] = *(const float2*)(brow1 + it * 64 + nt * 8);
        }

        if (it == 0) {
#pragma unroll
            for (int p = 0; p < 2; p++)
#pragma unroll
                for (int ks = 0; ks < 4; ks++) {
                    int row = wid * 16 + (lane & 15);
                    int un = (ks * 2 + (lane >> 4)) ^ (row & 7);
                    ldsm4(Qf[p][ks], sb + (uint32_t)(p * 8192) + row * 128 + un * 16);
                }
        }
        const uint32_t Kb = sb + 16384u + (uint32_t)((it & 1) * 32768);
        const uint32_t Vb = Kb + 16384u;

        // ---- S = Q.K^T  (K-fragment double buffering) ----
        float S[8][4];
#pragma unroll
        for (int nt = 0; nt < 8; nt++)
#pragma unroll
            for (int j = 0; j < 4; j++) S[nt][j] = 0.f;

        uint32_t Bf[2][2][4][4];
        auto load_k = [&](int ks, int fb) {
#pragma unroll
            for (int p = 0; p < 2; p++)
#pragma unroll
                for (int g = 0; g < 4; g++) {
                    int row = g * 16 + (lane & 15);
                    int un = (ks * 2 + (lane >> 4)) ^ (row & 7);
                    ldsm4(Bf[fb][p][g], Kb + (uint32_t)(p * 8192) + row * 128 + un * 16);
                }
        };
        load_k(0, 0);
#pragma unroll
        for (int ks = 0; ks < 4; ks++) {
            const int cur = ks & 1;
            if (ks < 3) load_k(ks + 1, cur ^ 1);
#pragma unroll
            for (int pass = 0; pass < 3; pass++) {
                const int ap = (pass == 2) ? 1 : 0;
                const int bp = (pass == 1) ? 1 : 0;
#pragma unroll
                for (int g = 0; g < 4; g++) {
                    mma_f16(S[2 * g],     Qf[ap][ks], Bf[cur][bp][g][0], Bf[cur][bp][g][2]);
                    mma_f16(S[2 * g + 1], Qf[ap][ks], Bf[cur][bp][g][1], Bf[cur][bp][g][3]);
                }
            }
        }

        // ---- bias + scale + causal mask ----
        const bool diag = (it == ntiles - 1);
#pragma unroll
        for (int nt = 0; nt < 8; nt++) {
            S[nt][0] = (S[nt][0] + bv0[nt].x) * 8.f;
            S[nt][1] = (S[nt][1] + bv0[nt].y) * 8.f;
            S[nt][2] = (S[nt][2] + bv1[nt].x) * 8.f;
            S[nt][3] = (S[nt][3] + bv1[nt].y) * 8.f;
            if (diag) {
                int cg = it * 64 + nt * 8 + (lane & 3) * 2;
                if (cg     > r0g) S[nt][0] = -1e30f;
                if (cg + 1 > r0g) S[nt][1] = -1e30f;
                if (cg     > r1g) S[nt][2] = -1e30f;
                if (cg + 1 > r1g) S[nt][3] = -1e30f;
            }
        }

        // ---- online softmax ----
        float mx0 = -1e30f, mx1 = -1e30f;
#pragma unroll
        for (int nt = 0; nt < 8; nt++) {
            mx0 = fmaxf(mx0, fmaxf(S[nt][0], S[nt][1]));
            mx1 = fmaxf(mx1, fmaxf(S[nt][2], S[nt][3]));
        }
        mx0 = fmaxf(mx0, __shfl_xor_sync(0xFFFFFFFF, mx0, 1));
        mx0 = fmaxf(mx0, __shfl_xor_sync(0xFFFFFFFF, mx0, 2));
        mx1 = fmaxf(mx1, __shfl_xor_sync(0xFFFFFFFF, mx1, 1));
        mx1 = fmaxf(mx1, __shfl_xor_sync(0xFFFFFFFF, mx1, 2));
        float mn0 = fmaxf(m0r, mx0), mn1 = fmaxf(m1r, mx1);
        float sc0 = __expf(m0r - mn0), sc1 = __expf(m1r - mn1);
        m0r = mn0; m1r = mn1;

        float sum0 = 0.f, sum1 = 0.f;
        uint32_t Ph[4][4];
#pragma unroll
        for (int ks = 0; ks < 4; ks++) {
#pragma unroll
            for (int half_ = 0; half_ < 2; half_++) {
                int nt = 2 * ks + half_;
                float p0 = __expf(S[nt][0] - mn0);
                float p1 = __expf(S[nt][1] - mn0);
                float p2 = __expf(S[nt][2] - mn1);
                float p3 = __expf(S[nt][3] - mn1);
                sum0 += p0 + p1; sum1 += p2 + p3;
                Ph[ks][half_ * 2]     = pack2h(p0, p1);
                Ph[ks][half_ * 2 + 1] = pack2h(p2, p3);
            }
        }
        sum0 += __shfl_xor_sync(0xFFFFFFFF, sum0, 1);
        sum0 += __shfl_xor_sync(0xFFFFFFFF, sum0, 2);
        sum1 += __shfl_xor_sync(0xFFFFFFFF, sum1, 1);
        sum1 += __shfl_xor_sync(0xFFFFFFFF, sum1, 2);
        l0r = l0r * sc0 + sum0;
        l1r = l1r * sc1 + sum1;
#pragma unroll
        for (int nt = 0; nt < 8; nt++) {
            y[nt][0] *= sc0; y[nt][1] *= sc0;
            y[nt][2] *= sc1; y[nt][3] *= sc1;
        }

        // ---- y += P.V  (2 passes: Ph*Vh, Ph*Vl) ----
#pragma unroll
        for (int ks = 0; ks < 4; ks++) {
            uint32_t Vf[2][4][4];
#pragma unroll
            for (int p = 0; p < 2; p++)
#pragma unroll
                for (int dc = 0; dc < 4; dc++) {
                    int row = ks * 16 + (lane & 15);
                    int un = (2 * dc + (lane >> 4)) ^ (row & 7);
                    ldsm4t(Vf[p][dc], Vb + (uint32_t)(p * 8192) + row * 128 + un * 16);
                }
#pragma unroll
            for (int vp = 0; vp < 2; vp++) {
#pragma unroll
                for (int dc = 0; dc < 4; dc++) {
                    mma_f16(y[2 * dc],     Ph[ks], Vf[vp][dc][0], Vf[vp][dc][1]);
                    mma_f16(y[2 * dc + 1], Ph[ks], Vf[vp][dc][2], Vf[vp][dc][3]);
                }
            }
        }
        __syncthreads();
    }

    // ---- normalize, split-store to g_yh/g_yl [B*T][C] ----
    float inv0 = 1.f / l0r, inv1 = 1.f / l1r;
#pragma unroll
    for (int nt = 0; nt < 8; nt++) {
        int col = h * 64 + nt * 8 + (lane & 3) * 2;
        size_t row0 = (size_t)b * TT + r0g;
        size_t row1 = (size_t)b * TT + r1g;
        uint32_t hpk, lpk;
        split_pack(y[nt][0] * inv0, y[nt][1] * inv0, hpk, lpk);
        *(uint32_t*)(g_yh + row0 * CC + col) = hpk;
        *(uint32_t*)(g_yl + row0 * CC + col) = lpk;
        split_pack(y[nt][2] * inv1, y[nt][3] * inv1, hpk, lpk);
        *(uint32_t*)(g_yh + row1 * CC + col) = hpk;
        *(uint32_t*)(g_yl + row1 * CC + col) = lpk;
    }
}

// ---------------------------------------------------------------------------
extern "C" void kernel_launch(void* const* d_in, const int* in_sizes, int n_in,
                              void* d_out, int out_size)
{
    const float* x    = (const float*)d_in[0];   // [B,T,C]
    const float* bias = (const float*)d_in[1];   // [1,H,T,T]
    const float* Wa   = (const float*)d_in[2];   // [3C,C]
    const float* Wp   = (const float*)d_in[3];   // [C,C]
    float* out = (float*)d_out;

    const int M = BB * TT;   // 4096

    void *xh, *xl, *wah, *wal, *wph, *wpl, *yh, *yl;
    cudaGetSymbolAddress(&xh, g_xh);   cudaGetSymbolAddress(&xl, g_xl);
    cudaGetSymbolAddress(&wah, g_wah); cudaGetSymbolAddress(&wal, g_wal);
    cudaGetSymbolAddress(&wph, g_wph); cudaGetSymbolAddress(&wpl, g_wpl);
    cudaGetSymbolAddress(&yh, g_yh);   cudaGetSymbolAddress(&yl, g_yl);

    cudaFuncSetAttribute(gemm_h2<1>, cudaFuncAttributeMaxDynamicSharedMemorySize, GEMM_SMEM);
    cudaFuncSetAttribute(gemm_h2<0>, cudaFuncAttributeMaxDynamicSharedMemorySize, GEMM_SMEM);
    cudaFuncSetAttribute(attn_mma,   cudaFuncAttributeMaxDynamicSharedMemorySize, ATTN_SMEM);

    // 0) fp32 -> fp16 hi/lo splits of inputs
    split2h<<<(M * CC + 255) / 256, 256>>>(x,  (__half*)xh,  (__half*)xl,  M * CC);
    split2h<<<(3 * CC * CC + 255) / 256, 256>>>(Wa, (__half*)wah, (__half*)wal, 3 * CC * CC);
    split2h<<<(CC * CC + 255) / 256, 256>>>(Wp, (__half*)wph, (__half*)wpl, CC * CC);

    // 1) QKV projection -> split q/k/v in [B,H,T,D]
    gemm_h2<1><<<dim3(3 * CC / 128, M / 128), 256, GEMM_SMEM>>>(
        (const __half*)xh, (const __half*)xl,
        (const __half*)wah, (const __half*)wal, nullptr, M, 3 * CC, CC);

    // 2) flash attention (HMMA) -> split y
    attn_mma<<<dim3(TT / 64, HH, BB), 128, ATTN_SMEM>>>(bias);

    // 3) output projection -> fp32 out
    gemm_h2<0><<<dim3(CC / 128, M / 128), 256, GEMM_SMEM>>>(
        (const __half*)yh, (const __half*)yl,
        (const __half*)wph, (const __half*)wpl, out, M, CC, CC);
}

// round 5
// speedup vs baseline: 3.0887x; 1.0643x over previous
#include <cuda_runtime.h>
#include <cuda_fp16.h>
#include <math.h>
#include <stdint.h>

#define BB 2
#define TT 2048
#define CC 1024
#define HH 16
#define DD 64

// ---------------- device scratch (allocation-free rule) ----------------
__device__ __half g_xh[4194304],  g_xl[4194304];    // x split        [4096][1024]
__device__ __half g_wah[3145728], g_wal[3145728];   // W_attn split   [3072][1024]
__device__ __half g_wph[1048576], g_wpl[1048576];   // W_proj split   [1024][1024]
__device__ __half g_qh[4194304],  g_ql[4194304];    // q split  [B,H,T,D]
__device__ __half g_kh[4194304],  g_kl[4194304];
__device__ __half g_vh[4194304],  g_vl[4194304];
__device__ __half g_yh[4194304],  g_yl[4194304];    // attn out split [4096][1024]

// ---------------- helpers ----------------
__device__ __forceinline__ uint32_t smem_u32(const void* p) {
    uint32_t a;
    asm("{ .reg .u64 t; cvta.to.shared.u64 t, %1; cvt.u32.u64 %0, t; }" : "=r"(a) : "l"(p));
    return a;
}

__device__ __forceinline__ void mma_f16(float* c, const uint32_t* a, uint32_t b0, uint32_t b1) {
    asm volatile(
        "mma.sync.aligned.m16n8k16.row.col.f32.f16.f16.f32 "
        "{%0,%1,%2,%3}, {%4,%5,%6,%7}, {%8,%9}, {%0,%1,%2,%3};\n"
        : "+f"(c[0]), "+f"(c[1]), "+f"(c[2]), "+f"(c[3])
        : "r"(a[0]), "r"(a[1]), "r"(a[2]), "r"(a[3]), "r"(b0), "r"(b1));
}
__device__ __forceinline__ void ldsm4(uint32_t* r, uint32_t addr) {
    asm volatile("ldmatrix.sync.aligned.m8n8.x4.shared.b16 {%0,%1,%2,%3}, [%4];"
                 : "=r"(r[0]), "=r"(r[1]), "=r"(r[2]), "=r"(r[3]) : "r"(addr));
}
__device__ __forceinline__ void ldsm4t(uint32_t* r, uint32_t addr) {
    asm volatile("ldmatrix.sync.aligned.m8n8.x4.trans.shared.b16 {%0,%1,%2,%3}, [%4];"
                 : "=r"(r[0]), "=r"(r[1]), "=r"(r[2]), "=r"(r[3]) : "r"(addr));
}
#define CP16(sa, g) asm volatile("cp.async.cg.shared.global [%0], [%1], 16;" :: "r"(sa), "l"(g) : "memory")
#define CP_COMMIT() asm volatile("cp.async.commit_group;" ::: "memory")
#define CP_WAIT1()  asm volatile("cp.async.wait_group 1;" ::: "memory")
#define CP_WAIT0()  asm volatile("cp.async.wait_group 0;" ::: "memory")

__device__ __forceinline__ void split_pack(float a, float b, uint32_t& hi, uint32_t& lo) {
    __half ha = __float2half_rn(a), hb = __float2half_rn(b);
    __half la = __float2half_rn(a - __half2float(ha));
    __half lb = __float2half_rn(b - __half2float(hb));
    __half2 H = __halves2half2(ha, hb), L = __halves2half2(la, lb);
    hi = *(uint32_t*)&H;  lo = *(uint32_t*)&L;
}
__device__ __forceinline__ uint32_t pack2h(float a, float b) {
    __half2 H = __halves2half2(__float2half_rn(a), __float2half_rn(b));
    return *(uint32_t*)&H;
}

// ---------------- fp32 -> fp16 hi/lo split ----------------
__global__ void split2h(const float* __restrict__ s, __half* __restrict__ hi,
                        __half* __restrict__ lo, int n) {
    int i = blockIdx.x * blockDim.x + threadIdx.x;
    if (i < n) {
        float v = s[i];
        __half h = __float2half_rn(v);
        hi[i] = h;
        lo[i] = __float2half_rn(v - __half2float(h));
    }
}

// ---------------------------------------------------------------------------
// HMMA fp16x2 GEMM: C[M,N] = A[M,K]*B[N,K]^T (3-pass split, fp32 accum)
// CTA tile 128x64, BK=64, 256 threads (8 warps, 4m x 2n -> warp 32x32),
// 32 accumulators/thread, 96KB smem double-buffer => 2 CTAs/SM.
// EPI=0: fp32 store to C.  EPI=1: split-store into g_{q,k,v}{h,l} [B,H,T,D].
// ---------------------------------------------------------------------------
#define GEMM_SMEM (2 * 49152)

template<int EPI>
__global__ __launch_bounds__(256, 2)
void gemm_h2(const __half* __restrict__ Ah, const __half* __restrict__ Al,
             const __half* __restrict__ Bh_, const __half* __restrict__ Bl_,
             float* __restrict__ C, int M, int N, int K)
{
    extern __shared__ char smem[];
    const uint32_t sb = smem_u32(smem);
    const int tid = threadIdx.x, lane = tid & 31, wid = tid >> 5;
    const int wm = wid >> 1, wn = wid & 1;
    const int m0 = blockIdx.y * 128, n0 = blockIdx.x * 64;

    // buffer layout: Ah 16KB | Al 16KB | Bh 8KB | Bl 8KB  (stride 48KB)
    auto issue = [&](int buf, int k0) {
        const uint32_t bb = sb + (uint32_t)(buf * 49152);
#pragma unroll
        for (int p = 0; p < 2; p++) {
            const __half* S = p ? Al : Ah;
#pragma unroll
            for (int u = 0; u < 4; u++) {
                int unit = tid + u * 256;            // 0..1023
                int r = unit >> 3, sg = unit & 7;
                uint32_t sa = bb + (uint32_t)(p * 16384) + r * 128 + ((sg ^ (r & 7)) << 4);
                CP16(sa, (const void*)(S + (size_t)(m0 + r) * K + k0 + sg * 8));
            }
        }
#pragma unroll
        for (int p = 0; p < 2; p++) {
            const __half* S = p ? Bl_ : Bh_;
#pragma unroll
            for (int u = 0; u < 2; u++) {
                int unit = tid + u * 256;            // 0..511
                int r = unit >> 3, sg = unit & 7;
                uint32_t sa = bb + 32768u + (uint32_t)(p * 8192) + r * 128 + ((sg ^ (r & 7)) << 4);
                CP16(sa, (const void*)(S + (size_t)(n0 + r) * K + k0 + sg * 8));
            }
        }
        CP_COMMIT();
    };

    float acc[2][4][4];
#pragma unroll
    for (int mt = 0; mt < 2; mt++)
#pragma unroll
        for (int nt = 0; nt < 4; nt++)
#pragma unroll
            for (int j = 0; j < 4; j++) acc[mt][nt][j] = 0.f;

    const int NC = K >> 6;
    issue(0, 0);
    for (int kc = 0; kc < NC; kc++) {
        const int buf = kc & 1;
        if (kc + 1 < NC) { issue(buf ^ 1, (kc + 1) * 64); CP_WAIT1(); }
        else CP_WAIT0();
        __syncthreads();

        const uint32_t Ab = sb + (uint32_t)(buf * 49152);
        const uint32_t Bb = Ab + 32768u;

#pragma unroll
        for (int ks = 0; ks < 4; ks++) {
            uint32_t Af[2][2][4];   // [part][mt]
            uint32_t Bf[2][2][4];   // [part][g]
#pragma unroll
            for (int p = 0; p < 2; p++) {
#pragma unroll
                for (int mt = 0; mt < 2; mt++) {
                    int row = wm * 32 + mt * 16 + (lane & 15);
                    int un = (ks * 2 + (lane >> 4)) ^ (row & 7);
                    ldsm4(Af[p][mt], Ab + (uint32_t)(p * 16384) + row * 128 + un * 16);
                }
#pragma unroll
                for (int g = 0; g < 2; g++) {
                    int row = wn * 32 + g * 16 + (lane & 15);
                    int un = (ks * 2 + (lane >> 4)) ^ (row & 7);
                    ldsm4(Bf[p][g], Bb + (uint32_t)(p * 8192) + row * 128 + un * 16);
                }
            }
#pragma unroll
            for (int pass = 0; pass < 3; pass++) {
                const int ap = (pass == 2) ? 1 : 0;
                const int bp = (pass == 1) ? 1 : 0;
#pragma unroll
                for (int mt = 0; mt < 2; mt++)
#pragma unroll
                    for (int g = 0; g < 2; g++) {
                        mma_f16(acc[mt][2 * g],     Af[ap][mt], Bf[bp][g][0], Bf[bp][g][2]);
                        mma_f16(acc[mt][2 * g + 1], Af[ap][mt], Bf[bp][g][1], Bf[bp][g][3]);
                    }
            }
        }
        __syncthreads();
    }

    // epilogue
#pragma unroll
    for (int mt = 0; mt < 2; mt++) {
        int r0 = m0 + wm * 32 + mt * 16 + (lane >> 2);
        int r1 = r0 + 8;
#pragma unroll
        for (int nt = 0; nt < 4; nt++) {
            int n = n0 + wn * 32 + nt * 8 + (lane & 3) * 2;
            if (EPI == 0) {
                *(float2*)(C + (size_t)r0 * N + n) = make_float2(acc[mt][nt][0], acc[mt][nt][1]);
                *(float2*)(C + (size_t)r1 * N + n) = make_float2(acc[mt][nt][2], acc[mt][nt][3]);
            } else {
                int which = n >> 10, rem = n & 1023;
                int h = rem >> 6, d = rem & 63;
                __half* dh = (which == 0) ? g_qh : ((which == 1) ? g_kh : g_vh);
                __half* dl = (which == 0) ? g_ql : ((which == 1) ? g_kl : g_vl);
#pragma unroll
                for (int half_ = 0; half_ < 2; half_++) {
                    int m = half_ ? r1 : r0;
                    float v0 = acc[mt][nt][half_ * 2], v1 = acc[mt][nt][half_ * 2 + 1];
                    int b = m >> 11, t = m & 2047;
                    size_t idx = (((size_t)b * HH + h) * TT + t) * DD + d;
                    uint32_t hpk, lpk;
                    split_pack(v0, v1, hpk, lpk);
                    *(uint32_t*)(dh + idx) = hpk;
                    *(uint32_t*)(dl + idx) = lpk;
                }
            }
        }
    }
}

// ---------------------------------------------------------------------------
// Flash attention on HMMA. CTA: 64 q-rows, 128 threads.
// QK^T: 3-pass fp16x2.  PV: 2-pass (Ph*Vh + Ph*Vl).
// K-fragment double buffering + bias prefetch. Reversed CTA order.
// smem: Q hi/lo (2x8KB) + KV double buffer (2 x 4 parts x 8KB) = 80KB
// ---------------------------------------------------------------------------
#define ATTN_SMEM (16384 + 2 * 32768)

__global__ __launch_bounds__(128)
void attn_mma(const float* __restrict__ bias)
{
    extern __shared__ char smem[];
    const uint32_t sb = smem_u32(smem);
    const int tid = threadIdx.x, lane = tid & 31, wid = tid >> 5;
    const int t0 = (int)(gridDim.x - 1 - blockIdx.x) * 64;   // heavy tiles first
    const int h = blockIdx.y, b = blockIdx.z;

    const size_t qoff  = ((size_t)(b * HH + h) * TT + t0) * DD;
    const size_t kvoff = (size_t)(b * HH + h) * TT * DD;

    // Q load (both parts) into smem — joins KV0's cp.async group
    {
        const __half* S[2] = {g_qh + qoff, g_ql + qoff};
#pragma unroll
        for (int p = 0; p < 2; p++)
#pragma unroll
            for (int u = 0; u < 4; u++) {
                int unit = tid + u * 128;          // 0..511
                int r = unit >> 3, sg = unit & 7;
                uint32_t sa = sb + (uint32_t)(p * 8192) + r * 128 + ((sg ^ (r & 7)) << 4);
                CP16(sa, (const void*)(S[p] + (size_t)r * 64 + sg * 8));
            }
    }
    const __half* kvsrc[4] = {g_kh + kvoff, g_kl + kvoff, g_vh + kvoff, g_vl + kvoff};
    auto kv_issue = [&](int buf, int s0) {
#pragma unroll
        for (int p = 0; p < 4; p++) {
            const __half* S = kvsrc[p] + (size_t)s0 * 64;
#pragma unroll
            for (int u = 0; u < 4; u++) {
                int unit = tid + u * 128;
                int r = unit >> 3, sg = unit & 7;
                uint32_t sa = sb + 16384u + (uint32_t)(buf * 32768 + p * 8192) + r * 128 + ((sg ^ (r & 7)) << 4);
                CP16(sa, (const void*)(S + (size_t)r * 64 + sg * 8));
            }
        }
        CP_COMMIT();
    };
    kv_issue(0, 0);

    float m0r = -1e30f, m1r = -1e30f, l0r = 0.f, l1r = 0.f;
    float y[8][4];
#pragma unroll
    for (int nt = 0; nt < 8; nt++)
#pragma unroll
        for (int j = 0; j < 4; j++) y[nt][j] = 0.f;

    uint32_t Qf[2][4][4];    // [part][ks]
    const int r0g = t0 + wid * 16 + (lane >> 2);
    const int r1g = r0g + 8;
    const int ntiles = t0 / 64 + 1;
    const float* brow0 = bias + ((size_t)h * TT + r0g) * TT + (lane & 3) * 2;
    const float* brow1 = bias + ((size_t)h * TT + r1g) * TT + (lane & 3) * 2;

    for (int it = 0; it < ntiles; it++) {
        if (it + 1 < ntiles) { kv_issue((it + 1) & 1, (it + 1) * 64); CP_WAIT1(); }
        else CP_WAIT0();
        __syncthreads();

        // bias prefetch (gmem latency hidden under S MMAs)
        float2 bv0[8], bv1[8];
#pragma unroll
        for (int nt = 0; nt < 8; nt++) {
            bv0[nt] = *(const float2*)(brow0 + it * 64 + nt * 8);
            bv1[nt] = *(const float2*)(brow1 + it * 64 + nt * 8);
        }

        if (it == 0) {
#pragma unroll
            for (int p = 0; p < 2; p++)
#pragma unroll
                for (int ks = 0; ks < 4; ks++) {
                    int row = wid * 16 + (lane & 15);
                    int un = (ks * 2 + (lane >> 4)) ^ (row & 7);
                    ldsm4(Qf[p][ks], sb + (uint32_t)(p * 8192) + row * 128 + un * 16);
                }
        }
        const uint32_t Kb = sb + 16384u + (uint32_t)((it & 1) * 32768);
        const uint32_t Vb = Kb + 16384u;

        // ---- S = Q.K^T  (K-fragment double buffering) ----
        float S[8][4];
#pragma unroll
        for (int nt = 0; nt < 8; nt++)
#pragma unroll
            for (int j = 0; j < 4; j++) S[nt][j] = 0.f;

        uint32_t Bf[2][2][4][4];
        auto load_k = [&](int ks, int fb) {
#pragma unroll
            for (int p = 0; p < 2; p++)
#pragma unroll
                for (int g = 0; g < 4; g++) {
                    int row = g * 16 + (lane & 15);
                    int un = (ks * 2 + (lane >> 4)) ^ (row & 7);
                    ldsm4(Bf[fb][p][g], Kb + (uint32_t)(p * 8192) + row * 128 + un * 16);
                }
        };
        load_k(0, 0);
#pragma unroll
        for (int ks = 0; ks < 4; ks++) {
            const int cur = ks & 1;
            if (ks < 3) load_k(ks + 1, cur ^ 1);
#pragma unroll
            for (int pass = 0; pass < 3; pass++) {
                const int ap = (pass == 2) ? 1 : 0;
                const int bp = (pass == 1) ? 1 : 0;
#pragma unroll
                for (int g = 0; g < 4; g++) {
                    mma_f16(S[2 * g],     Qf[ap][ks], Bf[cur][bp][g][0], Bf[cur][bp][g][2]);
                    mma_f16(S[2 * g + 1], Qf[ap][ks], Bf[cur][bp][g][1], Bf[cur][bp][g][3]);
                }
            }
        }

        // ---- bias + scale + causal mask ----
        const bool diag = (it == ntiles - 1);
#pragma unroll
        for (int nt = 0; nt < 8; nt++) {
            S[nt][0] = (S[nt][0] + bv0[nt].x) * 8.f;
            S[nt][1] = (S[nt][1] + bv0[nt].y) * 8.f;
            S[nt][2] = (S[nt][2] + bv1[nt].x) * 8.f;
            S[nt][3] = (S[nt][3] + bv1[nt].y) * 8.f;
            if (diag) {
                int cg = it * 64 + nt * 8 + (lane & 3) * 2;
                if (cg     > r0g) S[nt][0] = -1e30f;
                if (cg + 1 > r0g) S[nt][1] = -1e30f;
                if (cg     > r1g) S[nt][2] = -1e30f;
                if (cg + 1 > r1g) S[nt][3] = -1e30f;
            }
        }

        // ---- online softmax ----
        float mx0 = -1e30f, mx1 = -1e30f;
#pragma unroll
        for (int nt = 0; nt < 8; nt++) {
            mx0 = fmaxf(mx0, fmaxf(S[nt][0], S[nt][1]));
            mx1 = fmaxf(mx1, fmaxf(S[nt][2], S[nt][3]));
        }
        mx0 = fmaxf(mx0, __shfl_xor_sync(0xFFFFFFFF, mx0, 1));
        mx0 = fmaxf(mx0, __shfl_xor_sync(0xFFFFFFFF, mx0, 2));
        mx1 = fmaxf(mx1, __shfl_xor_sync(0xFFFFFFFF, mx1, 1));
        mx1 = fmaxf(mx1, __shfl_xor_sync(0xFFFFFFFF, mx1, 2));
        float mn0 = fmaxf(m0r, mx0), mn1 = fmaxf(m1r, mx1);
        float sc0 = __expf(m0r - mn0), sc1 = __expf(m1r - mn1);
        m0r = mn0; m1r = mn1;

        float sum0 = 0.f, sum1 = 0.f;
        uint32_t Ph[4][4];
#pragma unroll
        for (int ks = 0; ks < 4; ks++) {
#pragma unroll
            for (int half_ = 0; half_ < 2; half_++) {
                int nt = 2 * ks + half_;
                float p0 = __expf(S[nt][0] - mn0);
                float p1 = __expf(S[nt][1] - mn0);
                float p2 = __expf(S[nt][2] - mn1);
                float p3 = __expf(S[nt][3] - mn1);
                sum0 += p0 + p1; sum1 += p2 + p3;
                Ph[ks][half_ * 2]     = pack2h(p0, p1);
                Ph[ks][half_ * 2 + 1] = pack2h(p2, p3);
            }
        }
        sum0 += __shfl_xor_sync(0xFFFFFFFF, sum0, 1);
        sum0 += __shfl_xor_sync(0xFFFFFFFF, sum0, 2);
        sum1 += __shfl_xor_sync(0xFFFFFFFF, sum1, 1);
        sum1 += __shfl_xor_sync(0xFFFFFFFF, sum1, 2);
        l0r = l0r * sc0 + sum0;
        l1r = l1r * sc1 + sum1;
#pragma unroll
        for (int nt = 0; nt < 8; nt++) {
            y[nt][0] *= sc0; y[nt][1] *= sc0;
            y[nt][2] *= sc1; y[nt][3] *= sc1;
        }

        // ---- y += P.V  (2 passes: Ph*Vh, Ph*Vl) ----
#pragma unroll
        for (int ks = 0; ks < 4; ks++) {
            uint32_t Vf[2][4][4];
#pragma unroll
            for (int p = 0; p < 2; p++)
#pragma unroll
                for (int dc = 0; dc < 4; dc++) {
                    int row = ks * 16 + (lane & 15);
                    int un = (2 * dc + (lane >> 4)) ^ (row & 7);
                    ldsm4t(Vf[p][dc], Vb + (uint32_t)(p * 8192) + row * 128 + un * 16);
                }
#pragma unroll
            for (int vp = 0; vp < 2; vp++) {
#pragma unroll
                for (int dc = 0; dc < 4; dc++) {
                    mma_f16(y[2 * dc],     Ph[ks], Vf[vp][dc][0], Vf[vp][dc][1]);
                    mma_f16(y[2 * dc + 1], Ph[ks], Vf[vp][dc][2], Vf[vp][dc][3]);
                }
            }
        }
        __syncthreads();
    }

    // ---- normalize, split-store to g_yh/g_yl [B*T][C] ----
    float inv0 = 1.f / l0r, inv1 = 1.f / l1r;
#pragma unroll
    for (int nt = 0; nt < 8; nt++) {
        int col = h * 64 + nt * 8 + (lane & 3) * 2;
        size_t row0 = (size_t)b * TT + r0g;
        size_t row1 = (size_t)b * TT + r1g;
        uint32_t hpk, lpk;
        split_pack(y[nt][0] * inv0, y[nt][1] * inv0, hpk, lpk);
        *(uint32_t*)(g_yh + row0 * CC + col) = hpk;
        *(uint32_t*)(g_yl + row0 * CC + col) = lpk;
        split_pack(y[nt][2] * inv1, y[nt][3] * inv1, hpk, lpk);
        *(uint32_t*)(g_yh + row1 * CC + col) = hpk;
        *(uint32_t*)(g_yl + row1 * CC + col) = lpk;
    }
}

// ---------------------------------------------------------------------------
extern "C" void kernel_launch(void* const* d_in, const int* in_sizes, int n_in,
                              void* d_out, int out_size)
{
    const float* x    = (const float*)d_in[0];   // [B,T,C]
    const float* bias = (const float*)d_in[1];   // [1,H,T,T]
    const float* Wa   = (const float*)d_in[2];   // [3C,C]
    const float* Wp   = (const float*)d_in[3];   // [C,C]
    float* out = (float*)d_out;

    const int M = BB * TT;   // 4096

    void *xh, *xl, *wah, *wal, *wph, *wpl, *yh, *yl;
    cudaGetSymbolAddress(&xh, g_xh);   cudaGetSymbolAddress(&xl, g_xl);
    cudaGetSymbolAddress(&wah, g_wah); cudaGetSymbolAddress(&wal, g_wal);
    cudaGetSymbolAddress(&wph, g_wph); cudaGetSymbolAddress(&wpl, g_wpl);
    cudaGetSymbolAddress(&yh, g_yh);   cudaGetSymbolAddress(&yl, g_yl);

    cudaFuncSetAttribute(gemm_h2<1>, cudaFuncAttributeMaxDynamicSharedMemorySize, GEMM_SMEM);
    cudaFuncSetAttribute(gemm_h2<0>, cudaFuncAttributeMaxDynamicSharedMemorySize, GEMM_SMEM);
    cudaFuncSetAttribute(attn_mma,   cudaFuncAttributeMaxDynamicSharedMemorySize, ATTN_SMEM);

    // 0) fp32 -> fp16 hi/lo splits of inputs
    split2h<<<(M * CC + 255) / 256, 256>>>(x,  (__half*)xh,  (__half*)xl,  M * CC);
    split2h<<<(3 * CC * CC + 255) / 256, 256>>>(Wa, (__half*)wah, (__half*)wal, 3 * CC * CC);
    split2h<<<(CC * CC + 255) / 256, 256>>>(Wp, (__half*)wph, (__half*)wpl, CC * CC);

    // 1) QKV projection -> split q/k/v in [B,H,T,D]
    gemm_h2<1><<<dim3(3 * CC / 64, M / 128), 256, GEMM_SMEM>>>(
        (const __half*)xh, (const __half*)xl,
        (const __half*)wah, (const __half*)wal, nullptr, M, 3 * CC, CC);

    // 2) flash attention (HMMA) -> split y
    attn_mma<<<dim3(TT / 64, HH, BB), 128, ATTN_SMEM>>>(bias);

    // 3) output projection -> fp32 out
    gemm_h2<0><<<dim3(CC / 64, M / 128), 256, GEMM_SMEM>>>(
        (const __half*)yh, (const __half*)yl,
        (const __half*)wph, (const __half*)wpl, out, M, CC, CC);
}